// round 4
// baseline (speedup 1.0000x reference)
#include <cuda_runtime.h>
#include <math.h>

#define THREADS 128
#define OBS 127

typedef unsigned long long u64;

__device__ __forceinline__ u64 ffma2(u64 a, u64 b, u64 c) {
  u64 d; asm("fma.rn.f32x2 %0, %1, %2, %3;" : "=l"(d) : "l"(a), "l"(b), "l"(c)); return d;
}
__device__ __forceinline__ u64 fmul2(u64 a, u64 b) {
  u64 d; asm("mul.rn.f32x2 %0, %1, %2;" : "=l"(d) : "l"(a), "l"(b)); return d;
}
__device__ __forceinline__ u64 pack2(float lo, float hi) {
  u64 d; asm("mov.b64 %0, {%1, %2};" : "=l"(d) : "f"(lo), "f"(hi)); return d;
}
__device__ __forceinline__ void unpack2(u64 v, float& lo, float& hi) {
  asm("mov.b64 {%0, %1}, %2;" : "=f"(lo), "=f"(hi) : "l"(v));
}
__device__ __forceinline__ u64 bcast2(float x) { return pack2(x, x); }
__device__ __forceinline__ u64 relu2(u64 v) {
  float a, b; unpack2(v, a, b);
  return pack2(fmaxf(a, 0.0f), fmaxf(b, 0.0f));
}

// Shared layout (float offsets; every base is 16B-aligned).
enum {
  ENW1P = 0,      // 16 jp * 12
  OAW1P = 192,    // 16 jp * 12
  GW1P  = 384,    // 16 jp * 8
  EN_W2 = 512,    // 32*16
  EN_B2 = 1024,   // 16
  OA_W2 = 1040,   // 32*16
  OA_B2 = 1552,   // 16
  OA_G  = 1568,   // 16
  OA_BLN= 1584,   // 16
  G_W2  = 1600,   // 32*16
  G_B2  = 2112,   // 16
  G_G   = 2128,   // 16
  G_BLN = 2144,   // 16
  M_W1  = 2160,   // 48*32
  M_B1  = 3696,   // 32
  M_W2  = 3728,   // 32*32
  M_B2  = 4752,   // 32
  M_W3  = 4784,   // 32*2
  M_B3  = 4848,   // 2
  SW_TOTAL = 4852
};

__global__ void __launch_bounds__(THREADS, 2)
actor_kernel(
    const float* __restrict__ s_input,
    const float* __restrict__ en_w1, const float* __restrict__ en_b1,
    const float* __restrict__ en_w2, const float* __restrict__ en_b2,
    const float* __restrict__ oa_w1, const float* __restrict__ oa_b1,
    const float* __restrict__ oa_w2, const float* __restrict__ oa_b2,
    const float* __restrict__ oa_g,  const float* __restrict__ oa_bln,
    const float* __restrict__ g_w1,  const float* __restrict__ g_b1,
    const float* __restrict__ g_w2,  const float* __restrict__ g_b2,
    const float* __restrict__ g_g,   const float* __restrict__ g_bln,
    const float* __restrict__ m_w1,  const float* __restrict__ m_b1,
    const float* __restrict__ m_w2,  const float* __restrict__ m_b2,
    const float* __restrict__ m_w3,  const float* __restrict__ m_b3,
    float* __restrict__ out, int B)
{
  __shared__ float sw[SW_TOTAL];
  const int tid = threadIdx.x;

  for (int idx = tid; idx < 192; idx += THREADS) {           // EN: 4 inputs
    int jp = idx / 12, r = idx % 12, slot = r >> 1, half = r & 1, j = 2 * jp + half;
    float v = 0.0f;
    if (slot == 0) v = en_b1[j];
    else if (slot <= 4) v = en_w1[(slot - 1) * 32 + j];
    sw[ENW1P + idx] = v;
  }
  for (int idx = tid; idx < 192; idx += THREADS) {           // OA: 5 inputs
    int jp = idx / 12, r = idx % 12, slot = r >> 1, half = r & 1, j = 2 * jp + half;
    sw[OAW1P + idx] = (slot == 0) ? oa_b1[j] : oa_w1[(slot - 1) * 32 + j];
  }
  for (int idx = tid; idx < 128; idx += THREADS) {           // G: 3 inputs
    int jp = idx / 8, r = idx % 8, slot = r >> 1, half = r & 1, j = 2 * jp + half;
    sw[GW1P + idx] = (slot == 0) ? g_b1[j] : g_w1[(slot - 1) * 32 + j];
  }
  #define CP(off, src, n) \
    for (int i = tid; i < (n); i += THREADS) sw[(off) + i] = (src)[i];
  CP(EN_W2, en_w2, 512)  CP(EN_B2, en_b2, 16)
  CP(OA_W2, oa_w2, 512)  CP(OA_B2, oa_b2, 16)
  CP(OA_G,  oa_g,  16)   CP(OA_BLN, oa_bln, 16)
  CP(G_W2,  g_w2,  512)  CP(G_B2, g_b2, 16)
  CP(G_G,   g_g,   16)   CP(G_BLN, g_bln, 16)
  CP(M_W1,  m_w1,  1536) CP(M_B1, m_b1, 32)
  CP(M_W2,  m_w2,  1024) CP(M_B2, m_b2, 32)
  CP(M_W3,  m_w3,  64)   CP(M_B3, m_b3, 2)
  #undef CP
  __syncthreads();

  const int b0 = blockIdx.x * (THREADS * 2) + tid;
  const int b1 = b0 + THREADS;
  if (b0 >= B) return;
  const bool has1 = (b1 < B);

  const float* __restrict__ s0 = s_input + (size_t)b0 * OBS;
  const float* __restrict__ s1 = s_input + (size_t)(has1 ? b1 : b0) * OBS;
  const float* sp[2] = { s0, s1 };

  // ================= self MLP: 4 -> 32 -> 16, two rows =================
  u64 selfp[2][8];
  {
    const ulonglong2* bb = (const ulonglong2*)&sw[EN_B2];
    #pragma unroll
    for (int t = 0; t < 4; t++) {
      selfp[0][2*t] = bb[t].x; selfp[0][2*t+1] = bb[t].y;
      selfp[1][2*t] = bb[t].x; selfp[1][2*t+1] = bb[t].y;
    }
    u64 p[2][4];
    #pragma unroll
    for (int r = 0; r < 2; r++)
      #pragma unroll
      for (int i = 0; i < 4; i++) p[r][i] = bcast2(sp[r][i]);

    #pragma unroll 4
    for (int jp = 0; jp < 16; jp++) {
      const ulonglong2* rr = (const ulonglong2*)&sw[ENW1P + jp * 12];
      ulonglong2 q0 = rr[0], q1 = rr[1], q2 = rr[2];
      u64 A0[2], A1[2];
      #pragma unroll
      for (int r = 0; r < 2; r++) {
        u64 a = q0.x;
        a = ffma2(p[r][0], q0.y, a);
        a = ffma2(p[r][1], q1.x, a);
        a = ffma2(p[r][2], q1.y, a);
        a = ffma2(p[r][3], q2.x, a);
        float a0, a1; unpack2(a, a0, a1);
        A0[r] = bcast2(fmaxf(a0, 0.0f));
        A1[r] = bcast2(fmaxf(a1, 0.0f));
      }
      const ulonglong2* w = (const ulonglong2*)&sw[EN_W2 + jp * 32];
      #pragma unroll
      for (int q = 0; q < 4; q++) {
        ulonglong2 wv = w[q];
        #pragma unroll
        for (int r = 0; r < 2; r++) {
          selfp[r][2*q]   = ffma2(A0[r], wv.x, selfp[r][2*q]);
          selfp[r][2*q+1] = ffma2(A0[r], wv.y, selfp[r][2*q+1]);
        }
      }
      #pragma unroll
      for (int q = 0; q < 4; q++) {
        ulonglong2 wv = w[4 + q];
        #pragma unroll
        for (int r = 0; r < 2; r++) {
          selfp[r][2*q]   = ffma2(A1[r], wv.x, selfp[r][2*q]);
          selfp[r][2*q+1] = ffma2(A1[r], wv.y, selfp[r][2*q+1]);
        }
      }
    }
    #pragma unroll
    for (int r = 0; r < 2; r++)
      #pragma unroll
      for (int t = 0; t < 8; t++) selfp[r][t] = relu2(selfp[r][t]);
  }

  u64 otherp[2][8], foodp[2][8];

  // ================= attention branches (br 0 = other, br 1 = food) =================
  #pragma unroll 1
  for (int br = 0; br < 2; br++) {
    const int NENT = br ? 16 : 15;
    const int W1P  = br ? GW1P : OAW1P;
    const int W2   = br ? G_W2 : OA_W2;
    const int B2   = br ? G_B2 : OA_B2;
    const int GG   = br ? G_G  : OA_G;
    const int BLN  = br ? G_BLN: OA_BLN;

    float m[2] = { -1e30f, -1e30f }, dd[2] = { 0.0f, 0.0f };
    u64 acc[2][8];
    #pragma unroll
    for (int r = 0; r < 2; r++)
      #pragma unroll
      for (int t = 0; t < 8; t++) acc[r][t] = 0ULL;

    // hoist layer-2 bias
    u64 eb[8];
    {
      const ulonglong2* bb = (const ulonglong2*)&sw[B2];
      #pragma unroll
      for (int t = 0; t < 4; t++) { eb[2*t] = bb[t].x; eb[2*t+1] = bb[t].y; }
    }

    #pragma unroll 1
    for (int n = 0; n < NENT; n++) {
      u64 p[2][5];
      #pragma unroll
      for (int r = 0; r < 2; r++) {
        if (br == 0) {
          p[r][0] = bcast2(sp[r][4 + 2*n]);
          p[r][1] = bcast2(sp[r][5 + 2*n]);
          p[r][2] = bcast2(sp[r][34 + 2*n]);
          p[r][3] = bcast2(sp[r][35 + 2*n]);
          p[r][4] = bcast2(sp[r][64 + n]);
        } else {
          p[r][0] = bcast2(sp[r][79 + 3*n]);
          p[r][1] = bcast2(sp[r][80 + 3*n]);
          p[r][2] = bcast2(sp[r][81 + 3*n]);
        }
      }

      u64 e[2][8];
      #pragma unroll
      for (int r = 0; r < 2; r++)
        #pragma unroll
        for (int t = 0; t < 8; t++) e[r][t] = eb[t];

      #pragma unroll 4
      for (int jp = 0; jp < 16; jp++) {
        u64 A0[2], A1[2];
        if (br == 0) {
          const ulonglong2* rr = (const ulonglong2*)&sw[W1P + jp * 12];
          ulonglong2 q0 = rr[0], q1 = rr[1], q2 = rr[2];
          #pragma unroll
          for (int r = 0; r < 2; r++) {
            u64 a = q0.x;
            a = ffma2(p[r][0], q0.y, a);
            a = ffma2(p[r][1], q1.x, a);
            a = ffma2(p[r][2], q1.y, a);
            a = ffma2(p[r][3], q2.x, a);
            a = ffma2(p[r][4], q2.y, a);
            float a0, a1; unpack2(a, a0, a1);
            A0[r] = bcast2(fmaxf(a0, 0.0f));
            A1[r] = bcast2(fmaxf(a1, 0.0f));
          }
        } else {
          const ulonglong2* rr = (const ulonglong2*)&sw[W1P + jp * 8];
          ulonglong2 q0 = rr[0], q1 = rr[1];
          #pragma unroll
          for (int r = 0; r < 2; r++) {
            u64 a = q0.x;
            a = ffma2(p[r][0], q0.y, a);
            a = ffma2(p[r][1], q1.x, a);
            a = ffma2(p[r][2], q1.y, a);
            float a0, a1; unpack2(a, a0, a1);
            A0[r] = bcast2(fmaxf(a0, 0.0f));
            A1[r] = bcast2(fmaxf(a1, 0.0f));
          }
        }
        const ulonglong2* w = (const ulonglong2*)&sw[W2 + jp * 32];
        #pragma unroll
        for (int q = 0; q < 4; q++) {
          ulonglong2 wv = w[q];
          #pragma unroll
          for (int r = 0; r < 2; r++) {
            e[r][2*q]   = ffma2(A0[r], wv.x, e[r][2*q]);
            e[r][2*q+1] = ffma2(A0[r], wv.y, e[r][2*q+1]);
          }
        }
        #pragma unroll
        for (int q = 0; q < 4; q++) {
          ulonglong2 wv = w[4 + q];
          #pragma unroll
          for (int r = 0; r < 2; r++) {
            e[r][2*q]   = ffma2(A1[r], wv.x, e[r][2*q]);
            e[r][2*q+1] = ffma2(A1[r], wv.y, e[r][2*q+1]);
          }
        }
      }

      #pragma unroll
      for (int r = 0; r < 2; r++) {
        u64 sc2 = 0ULL;
        #pragma unroll
        for (int t = 0; t < 8; t++) {
          e[r][t] = relu2(e[r][t]);
          sc2 = ffma2(selfp[r][t], e[r][t], sc2);
        }
        float slo, shi; unpack2(sc2, slo, shi);
        const float sc = (slo + shi) * 0.25f;

        const float mn = fmaxf(m[r], sc);
        const float f  = __expf(m[r] - mn);
        const float pe = __expf(sc - mn);
        dd[r] = dd[r] * f + pe;
        const u64 F = bcast2(f), P = bcast2(pe);
        #pragma unroll
        for (int t = 0; t < 8; t++) acc[r][t] = ffma2(acc[r][t], F, fmul2(P, e[r][t]));
        m[r] = mn;
      }
    }

    const u64* gp  = (const u64*)&sw[GG];
    const u64* blp = (const u64*)&sw[BLN];
    #pragma unroll
    for (int r = 0; r < 2; r++) {
      const float inv = 1.0f / dd[r];
      float att[16], mu = 0.0f;
      #pragma unroll
      for (int t = 0; t < 8; t++) {
        float a0, a1; unpack2(acc[r][t], a0, a1);
        att[2*t] = a0 * inv; att[2*t+1] = a1 * inv;
        mu += att[2*t] + att[2*t+1];
      }
      mu *= (1.0f / 16.0f);
      float var = 0.0f;
      #pragma unroll
      for (int k = 0; k < 16; k++) { const float t = att[k] - mu; var = fmaf(t, t, var); }
      var *= (1.0f / 16.0f);
      const float isd = rsqrtf(var + 1e-5f);
      u64* dst = br ? foodp[r] : otherp[r];
      #pragma unroll
      for (int t = 0; t < 8; t++) {
        const u64 y = pack2((att[2*t] - mu) * isd, (att[2*t+1] - mu) * isd);
        dst[t] = relu2(ffma2(y, gp[t], blp[t]));
      }
    }
  }

  // ================= merge head: 48 -> 32 -> 32 -> 2, two rows =================
  u64 h1[2][16];
  {
    const ulonglong2* bm = (const ulonglong2*)&sw[M_B1];
    #pragma unroll
    for (int t = 0; t < 8; t++) {
      h1[0][2*t] = bm[t].x; h1[0][2*t+1] = bm[t].y;
      h1[1][2*t] = bm[t].x; h1[1][2*t+1] = bm[t].y;
    }
  }
  #pragma unroll 1
  for (int seg = 0; seg < 3; seg++) {
    const int rowbase = seg * 16;
    #pragma unroll 2
    for (int t = 0; t < 8; t++) {
      u64 V0[2], V1[2];
      #pragma unroll
      for (int r = 0; r < 2; r++) {
        const u64 src = (seg == 0) ? selfp[r][t] : (seg == 1) ? foodp[r][t] : otherp[r][t];
        float v0, v1; unpack2(src, v0, v1);
        V0[r] = bcast2(v0); V1[r] = bcast2(v1);
      }
      const ulonglong2* w0 = (const ulonglong2*)&sw[M_W1 + (rowbase + 2*t) * 32];
      #pragma unroll
      for (int q = 0; q < 8; q++) {
        ulonglong2 wv = w0[q];
        #pragma unroll
        for (int r = 0; r < 2; r++) {
          h1[r][2*q]   = ffma2(V0[r], wv.x, h1[r][2*q]);
          h1[r][2*q+1] = ffma2(V0[r], wv.y, h1[r][2*q+1]);
        }
      }
      const ulonglong2* w1p = (const ulonglong2*)&sw[M_W1 + (rowbase + 2*t + 1) * 32];
      #pragma unroll
      for (int q = 0; q < 8; q++) {
        ulonglong2 wv = w1p[q];
        #pragma unroll
        for (int r = 0; r < 2; r++) {
          h1[r][2*q]   = ffma2(V1[r], wv.x, h1[r][2*q]);
          h1[r][2*q+1] = ffma2(V1[r], wv.y, h1[r][2*q+1]);
        }
      }
    }
  }

  u64 h2[2][16];
  {
    const ulonglong2* bm = (const ulonglong2*)&sw[M_B2];
    #pragma unroll
    for (int t = 0; t < 8; t++) {
      h2[0][2*t] = bm[t].x; h2[0][2*t+1] = bm[t].y;
      h2[1][2*t] = bm[t].x; h2[1][2*t+1] = bm[t].y;
    }
  }
  #pragma unroll 2
  for (int t = 0; t < 16; t++) {
    u64 V0[2], V1[2];
    #pragma unroll
    for (int r = 0; r < 2; r++) {
      float v0, v1; unpack2(h1[r][t], v0, v1);
      v0 = fmaxf(v0, 0.01f * v0);
      v1 = fmaxf(v1, 0.01f * v1);
      V0[r] = bcast2(v0); V1[r] = bcast2(v1);
    }
    const ulonglong2* w0 = (const ulonglong2*)&sw[M_W2 + (2*t) * 32];
    #pragma unroll
    for (int q = 0; q < 8; q++) {
      ulonglong2 wv = w0[q];
      #pragma unroll
      for (int r = 0; r < 2; r++) {
        h2[r][2*q]   = ffma2(V0[r], wv.x, h2[r][2*q]);
        h2[r][2*q+1] = ffma2(V0[r], wv.y, h2[r][2*q+1]);
      }
    }
    const ulonglong2* w1p = (const ulonglong2*)&sw[M_W2 + (2*t + 1) * 32];
    #pragma unroll
    for (int q = 0; q < 8; q++) {
      ulonglong2 wv = w1p[q];
      #pragma unroll
      for (int r = 0; r < 2; r++) {
        h2[r][2*q]   = ffma2(V1[r], wv.x, h2[r][2*q]);
        h2[r][2*q+1] = ffma2(V1[r], wv.y, h2[r][2*q+1]);
      }
    }
  }

  const u64* w3 = (const u64*)&sw[M_W3];
  #pragma unroll
  for (int r = 0; r < 2; r++) {
    u64 o2 = *(const u64*)&sw[M_B3];
    #pragma unroll
    for (int t = 0; t < 16; t++) {
      float v0, v1; unpack2(h2[r][t], v0, v1);
      v0 = fmaxf(v0, 0.01f * v0);
      v1 = fmaxf(v1, 0.01f * v1);
      o2 = ffma2(bcast2(v0), w3[2*t], o2);
      o2 = ffma2(bcast2(v1), w3[2*t + 1], o2);
    }
    float o0, o1; unpack2(o2, o0, o1);
    if (r == 0) {
      float2 res; res.x = tanhf(o0); res.y = tanhf(o1);
      *(float2*)&out[(size_t)b0 * 2] = res;
    } else if (has1) {
      float2 res; res.x = tanhf(o0); res.y = tanhf(o1);
      *(float2*)&out[(size_t)b1 * 2] = res;
    }
  }
}

extern "C" void kernel_launch(void* const* d_in, const int* in_sizes, int n_in,
                              void* d_out, int out_size)
{
  const float* s = (const float*)d_in[0];
  const int B = in_sizes[0] / OBS;
  const int rows_per_block = THREADS * 2;
  const int blocks = (B + rows_per_block - 1) / rows_per_block;

  actor_kernel<<<blocks, THREADS>>>(
      s,
      (const float*)d_in[1],  (const float*)d_in[2],
      (const float*)d_in[3],  (const float*)d_in[4],
      (const float*)d_in[5],  (const float*)d_in[6],
      (const float*)d_in[7],  (const float*)d_in[8],
      (const float*)d_in[9],  (const float*)d_in[10],
      (const float*)d_in[11], (const float*)d_in[12],
      (const float*)d_in[13], (const float*)d_in[14],
      (const float*)d_in[15], (const float*)d_in[16],
      (const float*)d_in[17], (const float*)d_in[18],
      (const float*)d_in[19], (const float*)d_in[20],
      (const float*)d_in[21], (const float*)d_in[22],
      (float*)d_out, B);
}